// round 2
// baseline (speedup 1.0000x reference)
#include <cuda_runtime.h>
#include <math.h>

// ---------------------------------------------------------------------------
// Problem constants (from reference): B=2, S=2048, D=2048, H=16, HD=128.
//
// Algebraic reduction of the reference attention:
//   attn[b,h,i,:] = ( sum_{j<i} v_j  +  exp(s_ii) * v_i ) / D_i
//   D_i = i + sum_{j>=i} exp( q_i . k_j / sqrt(D) )
// so only the upper-triangle exp row sums + diagonal are needed from QK^T.
// ---------------------------------------------------------------------------

namespace {
constexpr int B_  = 2;
constexpr int S_  = 2048;
constexpr int D_  = 2048;
constexpr int H_  = 16;
constexpr int HD_ = 128;
constexpr int BH_ = B_ * H_;     // 32
constexpr int M_  = B_ * S_;     // 4096 rows for the projection GEMMs
constexpr int NC_ = 32;          // scan chunks per (b,h)
constexpr int CH_ = S_ / NC_;    // 64 rows per chunk

constexpr int BM = 128, BN = 128, BK = 16, TM = 8, TN = 8;
constexpr float SCALE = 0.02209708691207961f;  // 1/sqrt(2048)
}

// Scratch (static device arrays; no allocation in kernel_launch).
__device__ float g_q[M_ * D_];
__device__ float g_k[M_ * D_];
__device__ float g_v[M_ * D_];
__device__ float g_cc[M_ * D_];
__device__ float g_dinv[BH_ * S_];
__device__ float g_ediag[BH_ * S_];
__device__ float g_csum[BH_ * NC_ * HD_];

// ---------------------------------------------------------------------------
// C[M,N] = A[M,K] * Bw[N,K]^T + bias[N]    (both operands K-contiguous, "NT")
// 128x128 block tile, 8x8 per thread, BK=16, 256 threads.
// ---------------------------------------------------------------------------
__global__ __launch_bounds__(256, 2)
void gemm_nt_bias(const float* __restrict__ A, const float* __restrict__ Bw,
                  const float* __restrict__ bias, float* __restrict__ C,
                  int M, int N, int K) {
  __shared__ __align__(16) float As[BK][BM + 4];
  __shared__ __align__(16) float Bs[BK][BN + 4];
  const int tid = threadIdx.x;
  const int tx = tid & 15;
  const int ty = tid >> 4;
  const long mBase = (long)blockIdx.y * BM;
  const long nBase = (long)blockIdx.x * BN;

  float acc[TM][TN];
#pragma unroll
  for (int u = 0; u < TM; ++u)
#pragma unroll
    for (int w = 0; w < TN; ++w) acc[u][w] = 0.0f;

  for (int k0 = 0; k0 < K; k0 += BK) {
#pragma unroll
    for (int it = 0; it < 2; ++it) {
      const int id  = tid + it * 256;
      const int row = id >> 2;
      const int c4  = (id & 3) << 2;
      float4 va = *(const float4*)(A + (mBase + row) * (long)K + k0 + c4);
      As[c4 + 0][row] = va.x; As[c4 + 1][row] = va.y;
      As[c4 + 2][row] = va.z; As[c4 + 3][row] = va.w;
      float4 vb = *(const float4*)(Bw + (nBase + row) * (long)K + k0 + c4);
      Bs[c4 + 0][row] = vb.x; Bs[c4 + 1][row] = vb.y;
      Bs[c4 + 2][row] = vb.z; Bs[c4 + 3][row] = vb.w;
    }
    __syncthreads();
#pragma unroll
    for (int kk = 0; kk < BK; ++kk) {
      float4 a0 = *(const float4*)&As[kk][ty * TM];
      float4 a1 = *(const float4*)&As[kk][ty * TM + 4];
      float4 b0 = *(const float4*)&Bs[kk][tx * TN];
      float4 b1 = *(const float4*)&Bs[kk][tx * TN + 4];
      const float a[TM] = {a0.x, a0.y, a0.z, a0.w, a1.x, a1.y, a1.z, a1.w};
      const float bb[TN] = {b0.x, b0.y, b0.z, b0.w, b1.x, b1.y, b1.z, b1.w};
#pragma unroll
      for (int u = 0; u < TM; ++u)
#pragma unroll
        for (int w = 0; w < TN; ++w) acc[u][w] += a[u] * bb[w];
    }
    __syncthreads();
  }

  float bv[TN];
#pragma unroll
  for (int w = 0; w < TN; ++w) bv[w] = bias[nBase + tx * TN + w];
#pragma unroll
  for (int u = 0; u < TM; ++u) {
    const long row = mBase + ty * TM + u;
    float* cp = C + row * (long)N + nBase + tx * TN;
    float4 o0 = make_float4(acc[u][0] + bv[0], acc[u][1] + bv[1],
                            acc[u][2] + bv[2], acc[u][3] + bv[3]);
    float4 o1 = make_float4(acc[u][4] + bv[4], acc[u][5] + bv[5],
                            acc[u][6] + bv[6], acc[u][7] + bv[7]);
    *(float4*)cp = o0;
    *(float4*)(cp + 4) = o1;
  }
}

// ---------------------------------------------------------------------------
// Per (b,h), per 128-row i-tile: loop j-tiles >= i-tile, compute 128x128
// score tiles (K-dim = HD = 128), then accumulate row sums of exp(s*scale)
// for j>=i and capture exp(diagonal). Writes dinv = 1/(i + rowsum), ediag.
// ---------------------------------------------------------------------------
__global__ __launch_bounds__(256, 2)
void qk_rowsum(const float* __restrict__ Q, const float* __restrict__ Km,
               float* __restrict__ dinv, float* __restrict__ ediag) {
  __shared__ __align__(16) float As[BK][BM + 4];
  __shared__ __align__(16) float Bs[BK][BN + 4];
  __shared__ float rsS[BM];

  const int it = blockIdx.x;          // i-tile (0..15)
  const int bh = blockIdx.y;          // 0..31
  const int b  = bh / H_;
  const int h  = bh % H_;
  const float* qb = Q  + (long)b * S_ * D_ + h * HD_;
  const float* kb = Km + (long)b * S_ * D_ + h * HD_;
  const long ibase = (long)it * BM;

  const int tid = threadIdx.x;
  const int tx = tid & 15;
  const int ty = tid >> 4;

  float rs[TM];
#pragma unroll
  for (int u = 0; u < TM; ++u) rs[u] = 0.0f;

  for (int jt = it; jt < S_ / BN; ++jt) {
    const long jbase = (long)jt * BN;
    float acc[TM][TN];
#pragma unroll
    for (int u = 0; u < TM; ++u)
#pragma unroll
      for (int w = 0; w < TN; ++w) acc[u][w] = 0.0f;

    for (int k0 = 0; k0 < HD_; k0 += BK) {
#pragma unroll
      for (int itr = 0; itr < 2; ++itr) {
        const int id  = tid + itr * 256;
        const int row = id >> 2;
        const int c4  = (id & 3) << 2;
        float4 va = *(const float4*)(qb + (ibase + row) * (long)D_ + k0 + c4);
        As[c4 + 0][row] = va.x; As[c4 + 1][row] = va.y;
        As[c4 + 2][row] = va.z; As[c4 + 3][row] = va.w;
        float4 vb = *(const float4*)(kb + (jbase + row) * (long)D_ + k0 + c4);
        Bs[c4 + 0][row] = vb.x; Bs[c4 + 1][row] = vb.y;
        Bs[c4 + 2][row] = vb.z; Bs[c4 + 3][row] = vb.w;
      }
      __syncthreads();
#pragma unroll
      for (int kk = 0; kk < BK; ++kk) {
        float4 a0 = *(const float4*)&As[kk][ty * TM];
        float4 a1 = *(const float4*)&As[kk][ty * TM + 4];
        float4 b0 = *(const float4*)&Bs[kk][tx * TN];
        float4 b1 = *(const float4*)&Bs[kk][tx * TN + 4];
        const float a[TM] = {a0.x, a0.y, a0.z, a0.w, a1.x, a1.y, a1.z, a1.w};
        const float bb[TN] = {b0.x, b0.y, b0.z, b0.w, b1.x, b1.y, b1.z, b1.w};
#pragma unroll
        for (int u = 0; u < TM; ++u)
#pragma unroll
          for (int w = 0; w < TN; ++w) acc[u][w] += a[u] * bb[w];
      }
      __syncthreads();
    }

    if (jt > it) {
      // entire tile has j > i
#pragma unroll
      for (int u = 0; u < TM; ++u)
#pragma unroll
        for (int w = 0; w < TN; ++w) rs[u] += __expf(acc[u][w] * SCALE);
    } else {
      // diagonal tile: mask j >= i, capture diagonal
#pragma unroll
      for (int u = 0; u < TM; ++u) {
        const int i = (int)ibase + ty * TM + u;
#pragma unroll
        for (int w = 0; w < TN; ++w) {
          const int j = (int)jbase + tx * TN + w;
          if (j > i) {
            rs[u] += __expf(acc[u][w] * SCALE);
          } else if (j == i) {
            const float e = __expf(acc[u][w] * SCALE);
            rs[u] += e;
            ediag[bh * S_ + i] = e;
          }
        }
      }
    }
  }

  if (tid < BM) rsS[tid] = 0.0f;
  __syncthreads();
#pragma unroll
  for (int u = 0; u < TM; ++u) atomicAdd(&rsS[ty * TM + u], rs[u]);
  __syncthreads();
  if (tid < BM) {
    const int i = (int)ibase + tid;
    dinv[bh * S_ + i] = 1.0f / ((float)i + rsS[tid]);
  }
}

// ---------------------------------------------------------------------------
// Exclusive prefix-sum of V along the sequence, per (b,h,hd); combine with
// ediag/dinv into concat layout [B,S,D] (channel = h*HD+hd).
// ---------------------------------------------------------------------------
__global__ void scan_pass1(const float* __restrict__ V, float* __restrict__ csum) {
  const int blk = blockIdx.x;
  const int bh = blk / NC_, c = blk % NC_;
  const int b = bh / H_, h = bh % H_;
  const int hd = threadIdx.x;
  const float* vp = V + (long)b * S_ * D_ + h * HD_ + hd;
  const int i0 = c * CH_;
  float s = 0.0f;
#pragma unroll 4
  for (int r = 0; r < CH_; ++r) s += vp[(long)(i0 + r) * D_];
  csum[(bh * NC_ + c) * HD_ + hd] = s;
}

__global__ void scan_pass2(const float* __restrict__ V, const float* __restrict__ csum,
                           const float* __restrict__ dinv, const float* __restrict__ ediag,
                           float* __restrict__ CC) {
  const int blk = blockIdx.x;
  const int bh = blk / NC_, c = blk % NC_;
  const int b = bh / H_, h = bh % H_;
  const int hd = threadIdx.x;
  const long base = (long)b * S_ * D_ + h * HD_ + hd;
  const float* vp = V + base;
  float* op = CC + base;
  const int i0 = c * CH_;

  float run = 0.0f;
  for (int c2 = 0; c2 < c; ++c2) run += csum[(bh * NC_ + c2) * HD_ + hd];

  for (int r = 0; r < CH_; ++r) {
    const int i = i0 + r;
    const float vv = vp[(long)i * D_];
    const float e  = ediag[bh * S_ + i];
    const float di = dinv[bh * S_ + i];
    op[(long)i * D_] = (run + e * vv) * di;
    run += vv;
  }
}

// ---------------------------------------------------------------------------
extern "C" void kernel_launch(void* const* d_in, const int* in_sizes, int n_in,
                              void* d_out, int out_size) {
  const float* x   = (const float*)d_in[0];
  const float* wq  = (const float*)d_in[1];
  const float* wqb = (const float*)d_in[2];
  const float* wk  = (const float*)d_in[3];
  const float* wkb = (const float*)d_in[4];
  const float* wv  = (const float*)d_in[5];
  const float* wvb = (const float*)d_in[6];
  const float* wo  = (const float*)d_in[7];
  const float* wob = (const float*)d_in[8];
  float* out = (float*)d_out;

  float *q, *k, *v, *cc, *dinv, *ediag, *csum;
  cudaGetSymbolAddress((void**)&q,     g_q);
  cudaGetSymbolAddress((void**)&k,     g_k);
  cudaGetSymbolAddress((void**)&v,     g_v);
  cudaGetSymbolAddress((void**)&cc,    g_cc);
  cudaGetSymbolAddress((void**)&dinv,  g_dinv);
  cudaGetSymbolAddress((void**)&ediag, g_ediag);
  cudaGetSymbolAddress((void**)&csum,  g_csum);

  const dim3 gg(D_ / BN, M_ / BM);   // (16, 32)
  gemm_nt_bias<<<gg, 256>>>(x, wq, wqb, q, M_, D_, D_);
  gemm_nt_bias<<<gg, 256>>>(x, wk, wkb, k, M_, D_, D_);
  gemm_nt_bias<<<gg, 256>>>(x, wv, wvb, v, M_, D_, D_);

  const dim3 gr(S_ / BM, BH_);       // (16, 32)
  qk_rowsum<<<gr, 256>>>(q, k, dinv, ediag);

  scan_pass1<<<BH_ * NC_, HD_>>>(v, csum);
  scan_pass2<<<BH_ * NC_, HD_>>>(v, csum, dinv, ediag, cc);

  gemm_nt_bias<<<gg, 256>>>(cc, wo, wob, out, M_, D_, D_);
}

// round 5
// speedup vs baseline: 2.7199x; 2.7199x over previous
#include <cuda_runtime.h>
#include <math.h>
#include <stdint.h>

// ---------------------------------------------------------------------------
// B=2, S=2048, D=2048, H=16, HD=128.
// attn[i] = ( sum_{j<i} v_j + exp(s_ii)*v_i ) / (i + sum_{j>=i} exp(s_ij))
// GEMMs + QK^T row-sums on tensor cores (tf32 mma.sync, fp32 accumulate).
// ---------------------------------------------------------------------------

namespace {
constexpr int B_  = 2;
constexpr int S_  = 2048;
constexpr int D_  = 2048;
constexpr int H_  = 16;
constexpr int HD_ = 128;
constexpr int BH_ = B_ * H_;     // 32
constexpr int M_  = B_ * S_;     // 4096
constexpr int NC_ = 32;
constexpr int CH_ = S_ / NC_;    // 64

constexpr int BM = 128, BN = 128, BK = 16;
constexpr int AST = BK + 4;      // smem row stride (20): frag LDS conflict-free
constexpr float SCALE = 0.02209708691207961f;  // 1/sqrt(2048)
}

// Scratch (static device arrays).
__device__ float g_q [(size_t)M_ * D_];
__device__ float g_k [(size_t)M_ * D_];
__device__ float g_v [(size_t)M_ * D_];
__device__ float g_cc[(size_t)M_ * D_];
__device__ float g_xr[(size_t)M_ * D_];
__device__ float g_wqr[(size_t)D_ * D_];
__device__ float g_wkr[(size_t)D_ * D_];
__device__ float g_wvr[(size_t)D_ * D_];
__device__ float g_wor[(size_t)D_ * D_];
__device__ float g_dinv [BH_ * S_];
__device__ float g_ediag[BH_ * S_];
__device__ float g_csum [BH_ * NC_ * HD_];

// ---------------------------------------------------------------------------
__device__ __forceinline__ uint32_t fbits(float x) { return __float_as_uint(x); }

__device__ __forceinline__ float rna_tf32(float x) {
  uint32_t u;
  asm("cvt.rna.tf32.f32 %0, %1;" : "=r"(u) : "f"(x));
  return __uint_as_float(u);
}

__device__ __forceinline__ void cp16(float* dst, const float* src) {
  uint32_t s = (uint32_t)__cvta_generic_to_shared(dst);
  asm volatile("cp.async.cg.shared.global [%0], [%1], 16;" :: "r"(s), "l"(src));
}
__device__ __forceinline__ void cp_commit() { asm volatile("cp.async.commit_group;"); }
template <int N> __device__ __forceinline__ void cp_wait() {
  asm volatile("cp.async.wait_group %0;" :: "n"(N));
}

__device__ __forceinline__ void mma8(float c[4], const uint32_t a[4],
                                     uint32_t b0, uint32_t b1) {
  asm volatile(
      "mma.sync.aligned.m16n8k8.row.col.f32.tf32.tf32.f32 "
      "{%0,%1,%2,%3},{%4,%5,%6,%7},{%8,%9},{%0,%1,%2,%3};"
      : "+f"(c[0]), "+f"(c[1]), "+f"(c[2]), "+f"(c[3])
      : "r"(a[0]), "r"(a[1]), "r"(a[2]), "r"(a[3]), "r"(b0), "r"(b1));
}

// Load one BK=16 stage of A(128 rows) and B(128 rows), both K-contiguous.
__device__ __forceinline__ void load_stage(float* sA, float* sB,
                                           const float* Ag, long ldA,
                                           const float* Bg, long ldB, int tid) {
  const int row = tid >> 2;
  const int c4  = (tid & 3) << 2;
  cp16(sA + row * AST + c4,        Ag + (long)row * ldA + c4);
  cp16(sA + (row + 64) * AST + c4, Ag + (long)(row + 64) * ldA + c4);
  cp16(sB + row * AST + c4,        Bg + (long)row * ldB + c4);
  cp16(sB + (row + 64) * AST + c4, Bg + (long)(row + 64) * ldB + c4);
}

// One BK=16 stage of mma: 2 k8 steps, warp tile 32x64 (2 m-tiles x 8 n-tiles).
__device__ __forceinline__ void compute_stage(const float* sA, const float* sB,
                                              int warpM, int warpN, int lane,
                                              float acc[2][8][4]) {
#pragma unroll
  for (int kk = 0; kk < 2; ++kk) {
    const int k = kk * 8 + (lane & 3);
    uint32_t a[2][4];
#pragma unroll
    for (int m = 0; m < 2; ++m) {
      const int r = warpM * 32 + m * 16 + (lane >> 2);
      a[m][0] = fbits(sA[r * AST + k]);
      a[m][1] = fbits(sA[(r + 8) * AST + k]);
      a[m][2] = fbits(sA[r * AST + k + 4]);
      a[m][3] = fbits(sA[(r + 8) * AST + k + 4]);
    }
#pragma unroll
    for (int n = 0; n < 8; ++n) {
      const int cix = warpN * 64 + n * 8 + (lane >> 2);
      const uint32_t b0 = fbits(sB[cix * AST + k]);
      const uint32_t b1 = fbits(sB[cix * AST + k + 4]);
      mma8(acc[0][n], a[0], b0, b1);
      mma8(acc[1][n], a[1], b0, b1);
    }
  }
}

// ---------------------------------------------------------------------------
// C[M,N] = A[M,K] * Bw[N,K]^T + bias, tf32 tensor-core, cp.async double buffer.
// ---------------------------------------------------------------------------
__global__ __launch_bounds__(256)
void gemm_tf32(const float* __restrict__ A, const float* __restrict__ Bw,
               const float* __restrict__ bias, float* __restrict__ C,
               int M, int N, int K, int roundOut) {
  __shared__ float sA[2][BM * AST];
  __shared__ float sB[2][BN * AST];
  const int tid = threadIdx.x, lane = tid & 31, warp = tid >> 5;
  const int warpM = warp & 3, warpN = warp >> 2;
  const long mBase = (long)blockIdx.y * BM;
  const long nBase = (long)blockIdx.x * BN;
  const float* Ab = A + mBase * (long)K;
  const float* Bb = Bw + nBase * (long)K;

  float acc[2][8][4];
#pragma unroll
  for (int m = 0; m < 2; ++m)
#pragma unroll
    for (int n = 0; n < 8; ++n)
#pragma unroll
      for (int c = 0; c < 4; ++c) acc[m][n][c] = 0.0f;

  load_stage(sA[0], sB[0], Ab, K, Bb, K, tid); cp_commit();
  load_stage(sA[1], sB[1], Ab + BK, K, Bb + BK, K, tid); cp_commit();

  const int nIter = K / BK;
  for (int it = 0; it < nIter; ++it) {
    if (it < nIter - 1) cp_wait<1>(); else cp_wait<0>();
    __syncthreads();
    compute_stage(sA[it & 1], sB[it & 1], warpM, warpN, lane, acc);
    __syncthreads();
    if (it + 2 < nIter) {
      const long ko = (long)(it + 2) * BK;
      load_stage(sA[it & 1], sB[it & 1], Ab + ko, K, Bb + ko, K, tid);
      cp_commit();
    }
  }

#pragma unroll
  for (int m = 0; m < 2; ++m) {
    const long r0 = mBase + warpM * 32 + m * 16 + (lane >> 2);
#pragma unroll
    for (int n = 0; n < 8; ++n) {
      const long col = nBase + warpN * 64 + n * 8 + (lane & 3) * 2;
      const float b0 = bias[col], b1 = bias[col + 1];
      float v0 = acc[m][n][0] + b0, v1 = acc[m][n][1] + b1;
      float v2 = acc[m][n][2] + b0, v3 = acc[m][n][3] + b1;
      if (roundOut) {
        v0 = rna_tf32(v0); v1 = rna_tf32(v1);
        v2 = rna_tf32(v2); v3 = rna_tf32(v3);
      }
      *(float2*)(C + r0 * (long)N + col)       = make_float2(v0, v1);
      *(float2*)(C + (r0 + 8) * (long)N + col) = make_float2(v2, v3);
    }
  }
}

// ---------------------------------------------------------------------------
// QK^T upper-triangle exp row sums, tensor-core scores.
// ---------------------------------------------------------------------------
__global__ __launch_bounds__(256)
void qk_rowsum_t(const float* __restrict__ Q, const float* __restrict__ Km,
                 float* __restrict__ dinv, float* __restrict__ ediag) {
  __shared__ float sA[2][BM * AST];
  __shared__ float sB[2][BN * AST];
  __shared__ float rsS[BM];
  const int tid = threadIdx.x, lane = tid & 31, warp = tid >> 5;
  const int warpM = warp & 3, warpN = warp >> 2;
  const int itile = blockIdx.x, bh = blockIdx.y;
  const int b = bh >> 4, h = bh & 15;
  const float* qb    = Q  + (long)b * S_ * D_ + (long)h * HD_ + (long)itile * BM * D_;
  const float* kbase = Km + (long)b * S_ * D_ + (long)h * HD_;

  if (tid < BM) rsS[tid] = 0.0f;
  float rs[4] = {0.0f, 0.0f, 0.0f, 0.0f};

  for (int jt = itile; jt < S_ / BN; ++jt) {
    const float* kb = kbase + (long)jt * BN * D_;
    float acc[2][8][4];
#pragma unroll
    for (int m = 0; m < 2; ++m)
#pragma unroll
      for (int n = 0; n < 8; ++n)
#pragma unroll
        for (int c = 0; c < 4; ++c) acc[m][n][c] = 0.0f;

    __syncthreads();  // protect smem from previous jt's readers
    load_stage(sA[0], sB[0], qb, D_, kb, D_, tid); cp_commit();
    load_stage(sA[1], sB[1], qb + BK, D_, kb + BK, D_, tid); cp_commit();

    const int nIter = HD_ / BK;  // 8
    for (int it2 = 0; it2 < nIter; ++it2) {
      if (it2 < nIter - 1) cp_wait<1>(); else cp_wait<0>();
      __syncthreads();
      compute_stage(sA[it2 & 1], sB[it2 & 1], warpM, warpN, lane, acc);
      __syncthreads();
      if (it2 + 2 < nIter) {
        const long ko = (long)(it2 + 2) * BK;
        load_stage(sA[it2 & 1], sB[it2 & 1], qb + ko, D_, kb + ko, D_, tid);
        cp_commit();
      }
    }

    if (jt > itile) {
#pragma unroll
      for (int m = 0; m < 2; ++m)
#pragma unroll
        for (int n = 0; n < 8; ++n) {
          rs[m * 2 + 0] += __expf(acc[m][n][0] * SCALE) + __expf(acc[m][n][1] * SCALE);
          rs[m * 2 + 1] += __expf(acc[m][n][2] * SCALE) + __expf(acc[m][n][3] * SCALE);
        }
    } else {
#pragma unroll
      for (int m = 0; m < 2; ++m) {
        const int li0 = warpM * 32 + m * 16 + (lane >> 2);
#pragma unroll
        for (int n = 0; n < 8; ++n) {
          const int lj = warpN * 64 + n * 8 + (lane & 3) * 2;
#pragma unroll
          for (int c = 0; c < 4; ++c) {
            const int li  = li0 + ((c >> 1) << 3);
            const int ljc = lj + (c & 1);
            if (ljc >= li) {
              const float e = __expf(acc[m][n][c] * SCALE);
              rs[m * 2 + (c >> 1)] += e;
              if (ljc == li) ediag[(long)bh * S_ + itile * BM + li] = e;
            }
          }
        }
      }
    }
  }

#pragma unroll
  for (int r = 0; r < 4; ++r) {
    rs[r] += __shfl_xor_sync(0xffffffffu, rs[r], 1);
    rs[r] += __shfl_xor_sync(0xffffffffu, rs[r], 2);
  }
  __syncthreads();
  if ((lane & 3) == 0) {
#pragma unroll
    for (int r = 0; r < 4; ++r) {
      const int li = warpM * 32 + (r >> 1) * 16 + (r & 1) * 8 + (lane >> 2);
      atomicAdd(&rsS[li], rs[r]);
    }
  }
  __syncthreads();
  if (tid < BM) {
    const int i = itile * BM + tid;
    dinv[(long)bh * S_ + i] = 1.0f / ((float)i + rsS[tid]);
  }
}

// ---------------------------------------------------------------------------
// RNA-round to tf32 (prepass for x and weights).
// ---------------------------------------------------------------------------
__global__ void round_tf32_k(const float4* __restrict__ in,
                             float4* __restrict__ out, int n4) {
  const int i = blockIdx.x * blockDim.x + threadIdx.x;
  if (i < n4) {
    float4 v = in[i];
    v.x = rna_tf32(v.x); v.y = rna_tf32(v.y);
    v.z = rna_tf32(v.z); v.w = rna_tf32(v.w);
    out[i] = v;
  }
}

// ---------------------------------------------------------------------------
// V prefix-sum / combine (unchanged except cc gets rounded to tf32).
// ---------------------------------------------------------------------------
__global__ void scan_pass1(const float* __restrict__ V, float* __restrict__ csum) {
  const int blk = blockIdx.x;
  const int bh = blk / NC_, c = blk % NC_;
  const int b = bh / H_, h = bh % H_;
  const int hd = threadIdx.x;
  const float* vp = V + (long)b * S_ * D_ + h * HD_ + hd;
  const int i0 = c * CH_;
  float s = 0.0f;
#pragma unroll 4
  for (int r = 0; r < CH_; ++r) s += vp[(long)(i0 + r) * D_];
  csum[(bh * NC_ + c) * HD_ + hd] = s;
}

__global__ void scan_pass2(const float* __restrict__ V, const float* __restrict__ csum,
                           const float* __restrict__ dinv, const float* __restrict__ ediag,
                           float* __restrict__ CC) {
  const int blk = blockIdx.x;
  const int bh = blk / NC_, c = blk % NC_;
  const int b = bh / H_, h = bh % H_;
  const int hd = threadIdx.x;
  const long base = (long)b * S_ * D_ + h * HD_ + hd;
  const float* vp = V + base;
  float* op = CC + base;
  const int i0 = c * CH_;

  float run = 0.0f;
  for (int c2 = 0; c2 < c; ++c2) run += csum[(bh * NC_ + c2) * HD_ + hd];

  for (int r = 0; r < CH_; ++r) {
    const int i = i0 + r;
    const float vv = vp[(long)i * D_];
    const float e  = ediag[bh * S_ + i];
    const float di = dinv[bh * S_ + i];
    op[(long)i * D_] = rna_tf32((run + e * vv) * di);
    run += vv;
  }
}

// ---------------------------------------------------------------------------
extern "C" void kernel_launch(void* const* d_in, const int* in_sizes, int n_in,
                              void* d_out, int out_size) {
  const float* x   = (const float*)d_in[0];
  const float* wq  = (const float*)d_in[1];
  const float* wqb = (const float*)d_in[2];
  const float* wk  = (const float*)d_in[3];
  const float* wkb = (const float*)d_in[4];
  const float* wv  = (const float*)d_in[5];
  const float* wvb = (const float*)d_in[6];
  const float* wo  = (const float*)d_in[7];
  const float* wob = (const float*)d_in[8];
  float* out = (float*)d_out;

  float *q, *k, *v, *cc, *xr, *wqr, *wkr, *wvr, *wor, *dinv, *ediag, *csum;
  cudaGetSymbolAddress((void**)&q,     g_q);
  cudaGetSymbolAddress((void**)&k,     g_k);
  cudaGetSymbolAddress((void**)&v,     g_v);
  cudaGetSymbolAddress((void**)&cc,    g_cc);
  cudaGetSymbolAddress((void**)&xr,    g_xr);
  cudaGetSymbolAddress((void**)&wqr,   g_wqr);
  cudaGetSymbolAddress((void**)&wkr,   g_wkr);
  cudaGetSymbolAddress((void**)&wvr,   g_wvr);
  cudaGetSymbolAddress((void**)&wor,   g_wor);
  cudaGetSymbolAddress((void**)&dinv,  g_dinv);
  cudaGetSymbolAddress((void**)&ediag, g_ediag);
  cudaGetSymbolAddress((void**)&csum,  g_csum);

  const int nx4 = M_ * D_ / 4;
  const int nw4 = D_ * D_ / 4;
  round_tf32_k<<<(nx4 + 255) / 256, 256>>>((const float4*)x,  (float4*)xr,  nx4);
  round_tf32_k<<<(nw4 + 255) / 256, 256>>>((const float4*)wq, (float4*)wqr, nw4);
  round_tf32_k<<<(nw4 + 255) / 256, 256>>>((const float4*)wk, (float4*)wkr, nw4);
  round_tf32_k<<<(nw4 + 255) / 256, 256>>>((const float4*)wv, (float4*)wvr, nw4);
  round_tf32_k<<<(nw4 + 255) / 256, 256>>>((const float4*)wo, (float4*)wor, nw4);

  const dim3 gg(D_ / BN, M_ / BM);   // (16, 32)
  gemm_tf32<<<gg, 256>>>(xr, wqr, wqb, q, M_, D_, D_, 1);
  gemm_tf32<<<gg, 256>>>(xr, wkr, wkb, k, M_, D_, D_, 1);
  gemm_tf32<<<gg, 256>>>(xr, wvr, wvb, v, M_, D_, D_, 0);

  const dim3 gr(S_ / BM, BH_);       // (16, 32)
  qk_rowsum_t<<<gr, 256>>>(q, k, dinv, ediag);

  scan_pass1<<<BH_ * NC_, HD_>>>(v, csum);
  scan_pass2<<<BH_ * NC_, HD_>>>(v, csum, dinv, ediag, cc);

  gemm_tf32<<<gg, 256>>>(cc, wor, wob, out, M_, D_, D_, 0);
}

// round 8
// speedup vs baseline: 4.9626x; 1.8245x over previous
#include <cuda_runtime.h>
#include <cuda_fp16.h>
#include <math.h>
#include <stdint.h>

// ---------------------------------------------------------------------------
// B=2, S=2048, D=2048, H=16, HD=128.
// attn[i] = ( sum_{j<i} v_j + exp(s_ii)*v_i ) / (i + sum_{j>=i} exp(s_ij))
// All GEMM-shaped work on fp16 mma.sync (m16n8k16, fp32 accumulate).
// (tcgen05 unusable: harness PTX target is sm_103 without the 'a'.)
// ---------------------------------------------------------------------------

namespace {
constexpr int B_  = 2;
constexpr int S_  = 2048;
constexpr int D_  = 2048;
constexpr int H_  = 16;
constexpr int HD_ = 128;
constexpr int BH_ = B_ * H_;     // 32
constexpr int M_  = B_ * S_;     // 4096
constexpr int NC_ = 32;
constexpr int CH_ = S_ / NC_;    // 64

constexpr int BKH = 32;          // K halfs per stage
constexpr int HST = 40;          // padded row stride (halfs): conflict-free
constexpr float SCALE = 0.02209708691207961f;  // 1/sqrt(2048)
}

// Scratch (static device arrays).
__device__ __half g_xh [(size_t)M_ * D_];
__device__ __half g_wqh[(size_t)D_ * D_];
__device__ __half g_wkh[(size_t)D_ * D_];
__device__ __half g_wvh[(size_t)D_ * D_];
__device__ __half g_woh[(size_t)D_ * D_];
__device__ __half g_qh [(size_t)M_ * D_];
__device__ __half g_kh [(size_t)M_ * D_];
__device__ __half g_cch[(size_t)M_ * D_];
__device__ float  g_v  [(size_t)M_ * D_];
__device__ float  g_dinv [BH_ * S_];
__device__ float  g_ediag[BH_ * S_];
__device__ float  g_csum [BH_ * NC_ * HD_];

// ---------------------------------------------------------------------------
__device__ __forceinline__ uint32_t h2u(__half2 h) {
  return *reinterpret_cast<uint32_t*>(&h);
}

__device__ __forceinline__ void cp16(void* dst, const void* src) {
  uint32_t s = (uint32_t)__cvta_generic_to_shared(dst);
  asm volatile("cp.async.cg.shared.global [%0], [%1], 16;" :: "r"(s), "l"(src));
}
__device__ __forceinline__ void cp_commit() { asm volatile("cp.async.commit_group;"); }
template <int N> __device__ __forceinline__ void cp_wait() {
  asm volatile("cp.async.wait_group %0;" :: "n"(N));
}

__device__ __forceinline__ void mma16(float c[4], const uint32_t a[4],
                                      uint32_t b0, uint32_t b1) {
  asm volatile(
      "mma.sync.aligned.m16n8k16.row.col.f32.f16.f16.f32 "
      "{%0,%1,%2,%3},{%4,%5,%6,%7},{%8,%9},{%0,%1,%2,%3};"
      : "+f"(c[0]), "+f"(c[1]), "+f"(c[2]), "+f"(c[3])
      : "r"(a[0]), "r"(a[1]), "r"(a[2]), "r"(a[3]), "r"(b0), "r"(b1));
}

// Load one BKH=32-half stage of A(128 rows) + B(128 rows), K-contiguous halfs.
__device__ __forceinline__ void load_stage(__half* sA, __half* sB,
                                           const __half* Ag, long ldA,
                                           const __half* Bg, long ldB, int tid) {
#pragma unroll
  for (int i = 0; i < 4; ++i) {
    const int id   = tid + i * 256;     // 0..1023
    const int half = id >> 9;           // 0=A, 1=B
    const int rid  = id & 511;
    const int row  = rid >> 2;
    const int c8   = (rid & 3) << 3;    // half offset within row
    if (half == 0) cp16(sA + row * HST + c8, Ag + (long)row * ldA + c8);
    else           cp16(sB + row * HST + c8, Bg + (long)row * ldB + c8);
  }
}

// One stage = two m16n8k16 k-steps. Warp tile 32x64.
__device__ __forceinline__ void compute_stage(const __half* sA, const __half* sB,
                                              int warpM, int warpN, int lane,
                                              float acc[2][8][4]) {
#pragma unroll
  for (int kk = 0; kk < 2; ++kk) {
    const int ko = kk * 16 + (lane & 3) * 2;
    uint32_t a[2][4];
#pragma unroll
    for (int m = 0; m < 2; ++m) {
      const int r = warpM * 32 + m * 16 + (lane >> 2);
      a[m][0] = *(const uint32_t*)(sA + r * HST + ko);
      a[m][1] = *(const uint32_t*)(sA + (r + 8) * HST + ko);
      a[m][2] = *(const uint32_t*)(sA + r * HST + ko + 8);
      a[m][3] = *(const uint32_t*)(sA + (r + 8) * HST + ko + 8);
    }
#pragma unroll
    for (int n = 0; n < 8; ++n) {
      const int cix = warpN * 64 + n * 8 + (lane >> 2);
      const uint32_t b0 = *(const uint32_t*)(sB + cix * HST + ko);
      const uint32_t b1 = *(const uint32_t*)(sB + cix * HST + ko + 8);
      mma16(acc[0][n], a[0], b0, b1);
      mma16(acc[1][n], a[1], b0, b1);
    }
  }
}

// ---------------------------------------------------------------------------
// C[M,N] = A[M,K](h) * Bw[N,K](h)^T + bias. Output fp16 (Ch) or fp32 (Cf).
// ---------------------------------------------------------------------------
__global__ __launch_bounds__(256)
void gemm_h(const __half* __restrict__ A, const __half* __restrict__ Bw,
            const float* __restrict__ bias, __half* __restrict__ Ch,
            float* __restrict__ Cf, int K) {
  __shared__ __align__(16) __half sA[2][128 * HST];
  __shared__ __align__(16) __half sB[2][128 * HST];
  const int tid = threadIdx.x, lane = tid & 31, warp = tid >> 5;
  const int warpM = warp & 3, warpN = warp >> 2;
  const long mBase = (long)blockIdx.y * 128;
  const long nBase = (long)blockIdx.x * 128;
  const __half* Ab = A + mBase * (long)K;
  const __half* Bb = Bw + nBase * (long)K;

  float acc[2][8][4];
#pragma unroll
  for (int m = 0; m < 2; ++m)
#pragma unroll
    for (int n = 0; n < 8; ++n)
#pragma unroll
      for (int c = 0; c < 4; ++c) acc[m][n][c] = 0.0f;

  load_stage(sA[0], sB[0], Ab, K, Bb, K, tid); cp_commit();
  load_stage(sA[1], sB[1], Ab + BKH, K, Bb + BKH, K, tid); cp_commit();

  const int nIter = K / BKH;
  for (int it = 0; it < nIter; ++it) {
    if (it < nIter - 1) cp_wait<1>(); else cp_wait<0>();
    __syncthreads();
    compute_stage(sA[it & 1], sB[it & 1], warpM, warpN, lane, acc);
    __syncthreads();
    if (it + 2 < nIter) {
      const long ko = (long)(it + 2) * BKH;
      load_stage(sA[it & 1], sB[it & 1], Ab + ko, K, Bb + ko, K, tid);
      cp_commit();
    }
  }

#pragma unroll
  for (int m = 0; m < 2; ++m) {
    const long r0 = mBase + warpM * 32 + m * 16 + (lane >> 2);
#pragma unroll
    for (int n = 0; n < 8; ++n) {
      const long col = nBase + warpN * 64 + n * 8 + (lane & 3) * 2;
      const float b0 = bias[col], b1 = bias[col + 1];
      const float v0 = acc[m][n][0] + b0, v1 = acc[m][n][1] + b1;
      const float v2 = acc[m][n][2] + b0, v3 = acc[m][n][3] + b1;
      if (Ch) {
        *(uint32_t*)(Ch + r0 * (long)D_ + col)       = h2u(__floats2half2_rn(v0, v1));
        *(uint32_t*)(Ch + (r0 + 8) * (long)D_ + col) = h2u(__floats2half2_rn(v2, v3));
      } else {
        *(float2*)(Cf + r0 * (long)D_ + col)       = make_float2(v0, v1);
        *(float2*)(Cf + (r0 + 8) * (long)D_ + col) = make_float2(v2, v3);
      }
    }
  }
}

// ---------------------------------------------------------------------------
// QK^T upper-triangle exp row sums (fp16 mma, fp32 accum/exp).
// ---------------------------------------------------------------------------
__global__ __launch_bounds__(256)
void qk_rowsum_h(const __half* __restrict__ Q, const __half* __restrict__ Km,
                 float* __restrict__ dinv, float* __restrict__ ediag) {
  __shared__ __align__(16) __half sA[2][128 * HST];
  __shared__ __align__(16) __half sB[2][128 * HST];
  __shared__ float rsS[128];
  const int tid = threadIdx.x, lane = tid & 31, warp = tid >> 5;
  const int warpM = warp & 3, warpN = warp >> 2;
  const int itile = blockIdx.x, bh = blockIdx.y;
  const int b = bh >> 4, h = bh & 15;
  const __half* qb    = Q  + (long)b * S_ * D_ + (long)h * HD_ + (long)itile * 128 * D_;
  const __half* kbase = Km + (long)b * S_ * D_ + (long)h * HD_;

  if (tid < 128) rsS[tid] = 0.0f;
  float rs[4] = {0.0f, 0.0f, 0.0f, 0.0f};

  for (int jt = itile; jt < S_ / 128; ++jt) {
    const __half* kb = kbase + (long)jt * 128 * D_;
    float acc[2][8][4];
#pragma unroll
    for (int m = 0; m < 2; ++m)
#pragma unroll
      for (int n = 0; n < 8; ++n)
#pragma unroll
        for (int c = 0; c < 4; ++c) acc[m][n][c] = 0.0f;

    __syncthreads();  // protect smem from previous jt readers
    load_stage(sA[0], sB[0], qb, D_, kb, D_, tid); cp_commit();
    load_stage(sA[1], sB[1], qb + BKH, D_, kb + BKH, D_, tid); cp_commit();

    const int nIter = HD_ / BKH;  // 4
    for (int it2 = 0; it2 < nIter; ++it2) {
      if (it2 < nIter - 1) cp_wait<1>(); else cp_wait<0>();
      __syncthreads();
      compute_stage(sA[it2 & 1], sB[it2 & 1], warpM, warpN, lane, acc);
      __syncthreads();
      if (it2 + 2 < nIter) {
        const long ko = (long)(it2 + 2) * BKH;
        load_stage(sA[it2 & 1], sB[it2 & 1], qb + ko, D_, kb + ko, D_, tid);
        cp_commit();
      }
    }

    if (jt > itile) {
#pragma unroll
      for (int m = 0; m < 2; ++m)
#pragma unroll
        for (int n = 0; n < 8; ++n) {
          rs[m * 2 + 0] += __expf(acc[m][n][0] * SCALE) + __expf(acc[m][n][1] * SCALE);
          rs[m * 2 + 1] += __expf(acc[m][n][2] * SCALE) + __expf(acc[m][n][3] * SCALE);
        }
    } else {
#pragma unroll
      for (int m = 0; m < 2; ++m) {
        const int li0 = warpM * 32 + m * 16 + (lane >> 2);
#pragma unroll
        for (int n = 0; n < 8; ++n) {
          const int lj = warpN * 64 + n * 8 + (lane & 3) * 2;
#pragma unroll
          for (int c = 0; c < 4; ++c) {
            const int li  = li0 + ((c >> 1) << 3);
            const int ljc = lj + (c & 1);
            if (ljc >= li) {
              const float e = __expf(acc[m][n][c] * SCALE);
              rs[m * 2 + (c >> 1)] += e;
              if (ljc == li) ediag[(long)bh * S_ + itile * 128 + li] = e;
            }
          }
        }
      }
    }
  }

#pragma unroll
  for (int r = 0; r < 4; ++r) {
    rs[r] += __shfl_xor_sync(0xffffffffu, rs[r], 1);
    rs[r] += __shfl_xor_sync(0xffffffffu, rs[r], 2);
  }
  __syncthreads();
  if ((lane & 3) == 0) {
#pragma unroll
    for (int r = 0; r < 4; ++r) {
      const int li = warpM * 32 + (r >> 1) * 16 + (r & 1) * 8 + (lane >> 2);
      atomicAdd(&rsS[li], rs[r]);
    }
  }
  __syncthreads();
  if (tid < 128) {
    const int i = itile * 128 + tid;
    dinv[(long)bh * S_ + i] = 1.0f / ((float)i + rsS[tid]);
  }
}

// ---------------------------------------------------------------------------
// fp32 -> fp16 conversion prepass (8 elems/thread).
// ---------------------------------------------------------------------------
__global__ void conv_h(const float4* __restrict__ in, uint4* __restrict__ out, int n8) {
  const int i = blockIdx.x * blockDim.x + threadIdx.x;
  if (i < n8) {
    const float4 v0 = in[2 * i], v1 = in[2 * i + 1];
    uint4 o;
    o.x = h2u(__floats2half2_rn(v0.x, v0.y));
    o.y = h2u(__floats2half2_rn(v0.z, v0.w));
    o.z = h2u(__floats2half2_rn(v1.x, v1.y));
    o.w = h2u(__floats2half2_rn(v1.z, v1.w));
    out[i] = o;
  }
}

// ---------------------------------------------------------------------------
// V prefix-sum / combine; cc written as fp16.
// ---------------------------------------------------------------------------
__global__ void scan_pass1(const float* __restrict__ V, float* __restrict__ csum) {
  const int blk = blockIdx.x;
  const int bh = blk / NC_, c = blk % NC_;
  const int b = bh / H_, h = bh % H_;
  const int hd = threadIdx.x;
  const float* vp = V + (long)b * S_ * D_ + h * HD_ + hd;
  const int i0 = c * CH_;
  float s = 0.0f;
#pragma unroll 4
  for (int r = 0; r < CH_; ++r) s += vp[(long)(i0 + r) * D_];
  csum[(bh * NC_ + c) * HD_ + hd] = s;
}

__global__ void scan_pass2(const float* __restrict__ V, const float* __restrict__ csum,
                           const float* __restrict__ dinv, const float* __restrict__ ediag,
                           __half* __restrict__ CC) {
  const int blk = blockIdx.x;
  const int bh = blk / NC_, c = blk % NC_;
  const int b = bh / H_, h = bh % H_;
  const int hd = threadIdx.x;
  const long base = (long)b * S_ * D_ + h * HD_ + hd;
  const float* vp = V + base;
  __half* op = CC + base;
  const int i0 = c * CH_;

  float run = 0.0f;
  for (int c2 = 0; c2 < c; ++c2) run += csum[(bh * NC_ + c2) * HD_ + hd];

  for (int r = 0; r < CH_; ++r) {
    const int i = i0 + r;
    const float vv = vp[(long)i * D_];
    const float e  = ediag[bh * S_ + i];
    const float di = dinv[bh * S_ + i];
    op[(long)i * D_] = __float2half_rn((run + e * vv) * di);
    run += vv;
  }
}

// ---------------------------------------------------------------------------
extern "C" void kernel_launch(void* const* d_in, const int* in_sizes, int n_in,
                              void* d_out, int out_size) {
  const float* x   = (const float*)d_in[0];
  const float* wq  = (const float*)d_in[1];
  const float* wqb = (const float*)d_in[2];
  const float* wk  = (const float*)d_in[3];
  const float* wkb = (const float*)d_in[4];
  const float* wv  = (const float*)d_in[5];
  const float* wvb = (const float*)d_in[6];
  const float* wo  = (const float*)d_in[7];
  const float* wob = (const float*)d_in[8];
  float* out = (float*)d_out;

  __half *xh, *wqh, *wkh, *wvh, *woh, *qh, *kh, *cch;
  float *v, *dinv, *ediag, *csum;
  cudaGetSymbolAddress((void**)&xh,    g_xh);
  cudaGetSymbolAddress((void**)&wqh,   g_wqh);
  cudaGetSymbolAddress((void**)&wkh,   g_wkh);
  cudaGetSymbolAddress((void**)&wvh,   g_wvh);
  cudaGetSymbolAddress((void**)&woh,   g_woh);
  cudaGetSymbolAddress((void**)&qh,    g_qh);
  cudaGetSymbolAddress((void**)&kh,    g_kh);
  cudaGetSymbolAddress((void**)&cch,   g_cch);
  cudaGetSymbolAddress((void**)&v,     g_v);
  cudaGetSymbolAddress((void**)&dinv,  g_dinv);
  cudaGetSymbolAddress((void**)&ediag, g_ediag);
  cudaGetSymbolAddress((void**)&csum,  g_csum);

  const int nx8 = M_ * D_ / 8;
  const int nw8 = D_ * D_ / 8;
  conv_h<<<(nx8 + 255) / 256, 256>>>((const float4*)x,  (uint4*)xh,  nx8);
  conv_h<<<(nw8 + 255) / 256, 256>>>((const float4*)wq, (uint4*)wqh, nw8);
  conv_h<<<(nw8 + 255) / 256, 256>>>((const float4*)wk, (uint4*)wkh, nw8);
  conv_h<<<(nw8 + 255) / 256, 256>>>((const float4*)wv, (uint4*)wvh, nw8);
  conv_h<<<(nw8 + 255) / 256, 256>>>((const float4*)wo, (uint4*)woh, nw8);

  const dim3 gg(D_ / 128, M_ / 128);   // (16, 32)
  gemm_h<<<gg, 256>>>(xh, wqh, wqb, qh, nullptr, D_);
  gemm_h<<<gg, 256>>>(xh, wkh, wkb, kh, nullptr, D_);
  gemm_h<<<gg, 256>>>(xh, wvh, wvb, nullptr, v, D_);

  const dim3 gr(S_ / 128, BH_);        // (16, 32)
  qk_rowsum_h<<<gr, 256>>>(qh, kh, dinv, ediag);

  scan_pass1<<<BH_ * NC_, HD_>>>(v, csum);
  scan_pass2<<<BH_ * NC_, HD_>>>(v, csum, dinv, ediag, cch);

  gemm_h<<<gg, 256>>>(cch, woh, wob, nullptr, out, D_);
}

// round 9
// speedup vs baseline: 7.3523x; 1.4815x over previous
#include <cuda_runtime.h>
#include <cuda_fp16.h>
#include <math.h>
#include <stdint.h>

// ---------------------------------------------------------------------------
// B=2, S=2048, D=2048, H=16, HD=128.
// attn[i] = ( sum_{j<i} v_j + exp(s_ii)*v_i ) / (i + sum_{j>=i} exp(s_ij))
// fp16 mma.sync m16n8k16 (fp32 accum), ldmatrix operands, SW128 swizzle,
// 3-stage cp.async rings. Q tile cached across the jt loop in qk_rowsum.
// ---------------------------------------------------------------------------

namespace {
constexpr int B_  = 2;
constexpr int S_  = 2048;
constexpr int D_  = 2048;
constexpr int H_  = 16;
constexpr int HD_ = 128;
constexpr int BH_ = B_ * H_;     // 32
constexpr int M_  = B_ * S_;     // 4096
constexpr int NC_ = 32;
constexpr int CH_ = S_ / NC_;    // 64

constexpr int KB    = 64;                  // K halfs per block (128B rows)
constexpr int TILEB = 128 * 128;           // bytes per 128-row x 64-half tile (16KB)
constexpr int NST   = 3;                   // pipeline stages
constexpr unsigned DS_GEMM = NST * 2 * TILEB;        // 98304
constexpr unsigned DS_QK   = 2 * TILEB + NST * TILEB; // 81920
constexpr float SCALE = 0.02209708691207961f;  // 1/sqrt(2048)
}

// Scratch (static device arrays).
__device__ __half g_xh [(size_t)M_ * D_];
__device__ __half g_wqh[(size_t)D_ * D_];
__device__ __half g_wkh[(size_t)D_ * D_];
__device__ __half g_wvh[(size_t)D_ * D_];
__device__ __half g_woh[(size_t)D_ * D_];
__device__ __half g_qh [(size_t)M_ * D_];
__device__ __half g_kh [(size_t)M_ * D_];
__device__ __half g_cch[(size_t)M_ * D_];
__device__ float  g_v  [(size_t)M_ * D_];
__device__ float  g_dinv [BH_ * S_];
__device__ float  g_ediag[BH_ * S_];
__device__ float  g_csum [BH_ * NC_ * HD_];

// ---------------------------------------------------------------------------
__device__ __forceinline__ uint32_t h2u(__half2 h) {
  return *reinterpret_cast<uint32_t*>(&h);
}

__device__ __forceinline__ void cp16s(uint32_t dst, const void* src) {
  asm volatile("cp.async.cg.shared.global [%0], [%1], 16;" :: "r"(dst), "l"(src));
}
__device__ __forceinline__ void cp_commit() { asm volatile("cp.async.commit_group;"); }
template <int N> __device__ __forceinline__ void cp_wait() {
  asm volatile("cp.async.wait_group %0;" :: "n"(N));
}

__device__ __forceinline__ void mma16(float c[4], const uint32_t a[4],
                                      uint32_t b0, uint32_t b1) {
  asm volatile(
      "mma.sync.aligned.m16n8k16.row.col.f32.f16.f16.f32 "
      "{%0,%1,%2,%3},{%4,%5,%6,%7},{%8,%9},{%0,%1,%2,%3};"
      : "+f"(c[0]), "+f"(c[1]), "+f"(c[2]), "+f"(c[3])
      : "r"(a[0]), "r"(a[1]), "r"(a[2]), "r"(a[3]), "r"(b0), "r"(b1));
}

__device__ __forceinline__ void ldm4(uint32_t r[4], uint32_t addr) {
  asm volatile("ldmatrix.sync.aligned.m8n8.x4.shared.b16 {%0,%1,%2,%3}, [%4];"
               : "=r"(r[0]), "=r"(r[1]), "=r"(r[2]), "=r"(r[3]) : "r"(addr));
}

#define SWZ(x) ((x) ^ (((x) >> 3) & 0x70))

// Load a 128-row x 64-half tile (g row stride ldK halfs) into swizzled smem.
__device__ __forceinline__ void ld_tile(uint32_t sbase, const __half* g,
                                        long ldK, int tid) {
#pragma unroll
  for (int i = 0; i < 4; ++i) {
    const int id  = tid + i * 256;     // 0..1023
    const int row = id >> 3;           // 0..127
    const int cb  = (id & 7) << 4;     // byte col
    const int off = row * 128 + cb;
    cp16s(sbase + SWZ(off), g + (long)row * ldK + (cb >> 1));
  }
}

// One 64-half K block: 4 k16 steps; warp tile 32x64; A [m][k], B [n][k].
__device__ __forceinline__ void mma_block(uint32_t aBase, uint32_t bBase,
                                          int warpM, int warpN, int lane,
                                          float acc[2][8][4]) {
  const int mi = lane >> 3;                 // matrix index 0..3
  const int rA = (lane & 7) + ((mi & 1) << 3);
  const int cA = (mi >> 1) << 4;
  const int rB = (lane & 7) + ((mi >> 1) << 3);
  const int cB = (mi & 1) << 4;
#pragma unroll
  for (int ks = 0; ks < 4; ++ks) {
    const int kb = ks * 32;
    uint32_t a[2][4];
#pragma unroll
    for (int m = 0; m < 2; ++m) {
      const int off = (warpM * 32 + m * 16 + rA) * 128 + kb + cA;
      ldm4(a[m], aBase + SWZ(off));
    }
#pragma unroll
    for (int p = 0; p < 4; ++p) {
      uint32_t b[4];
      const int off = (warpN * 64 + p * 16 + rB) * 128 + kb + cB;
      ldm4(b, bBase + SWZ(off));
      mma16(acc[0][2 * p],     a[0], b[0], b[1]);
      mma16(acc[1][2 * p],     a[1], b[0], b[1]);
      mma16(acc[0][2 * p + 1], a[0], b[2], b[3]);
      mma16(acc[1][2 * p + 1], a[1], b[2], b[3]);
    }
  }
}

// ---------------------------------------------------------------------------
// C[M,N] = A[M,K](h) * Bw[N,K](h)^T + bias. Output fp16 (Ch) or fp32 (Cf).
// ---------------------------------------------------------------------------
__global__ __launch_bounds__(256)
void gemm_h(const __half* __restrict__ A, const __half* __restrict__ Bw,
            const float* __restrict__ bias, __half* __restrict__ Ch,
            float* __restrict__ Cf, int K) {
  extern __shared__ __align__(128) uint8_t dyn[];
  const uint32_t sb = (uint32_t)__cvta_generic_to_shared(dyn);
  const int tid = threadIdx.x, lane = tid & 31, warp = tid >> 5;
  const int warpM = warp & 3, warpN = warp >> 2;
  const long mBase = (long)blockIdx.y * 128;
  const long nBase = (long)blockIdx.x * 128;
  const __half* Ab = A + mBase * (long)K;
  const __half* Bb = Bw + nBase * (long)K;

  float acc[2][8][4];
#pragma unroll
  for (int m = 0; m < 2; ++m)
#pragma unroll
    for (int n = 0; n < 8; ++n)
#pragma unroll
      for (int c = 0; c < 4; ++c) acc[m][n][c] = 0.0f;

  const int NIT = K / KB;  // 32
#pragma unroll
  for (int s = 0; s < NST; ++s) {
    ld_tile(sb + s * 2 * TILEB,         Ab + s * KB, K, tid);
    ld_tile(sb + s * 2 * TILEB + TILEB, Bb + s * KB, K, tid);
    cp_commit();
  }

  for (int it = 0; it < NIT; ++it) {
    const int slot = it % NST;
    cp_wait<NST - 1>();
    __syncthreads();
    mma_block(sb + slot * 2 * TILEB, sb + slot * 2 * TILEB + TILEB,
              warpM, warpN, lane, acc);
    __syncthreads();
    if (it + NST < NIT) {
      ld_tile(sb + slot * 2 * TILEB,         Ab + (long)(it + NST) * KB, K, tid);
      ld_tile(sb + slot * 2 * TILEB + TILEB, Bb + (long)(it + NST) * KB, K, tid);
      cp_commit();
    }
  }

#pragma unroll
  for (int m = 0; m < 2; ++m) {
    const long r0 = mBase + warpM * 32 + m * 16 + (lane >> 2);
#pragma unroll
    for (int n = 0; n < 8; ++n) {
      const long col = nBase + warpN * 64 + n * 8 + (lane & 3) * 2;
      const float b0 = bias[col], b1 = bias[col + 1];
      const float v0 = acc[m][n][0] + b0, v1 = acc[m][n][1] + b1;
      const float v2 = acc[m][n][2] + b0, v3 = acc[m][n][3] + b1;
      if (Ch) {
        *(uint32_t*)(Ch + r0 * (long)D_ + col)       = h2u(__floats2half2_rn(v0, v1));
        *(uint32_t*)(Ch + (r0 + 8) * (long)D_ + col) = h2u(__floats2half2_rn(v2, v3));
      } else {
        *(float2*)(Cf + r0 * (long)D_ + col)       = make_float2(v0, v1);
        *(float2*)(Cf + (r0 + 8) * (long)D_ + col) = make_float2(v2, v3);
      }
    }
  }
}

// ---------------------------------------------------------------------------
// QK^T upper-triangle exp row sums. Q tile cached in smem; K tiles streamed.
// ---------------------------------------------------------------------------
__global__ __launch_bounds__(256)
void qk_rowsum_h(const __half* __restrict__ Q, const __half* __restrict__ Km,
                 float* __restrict__ dinv, float* __restrict__ ediag) {
  extern __shared__ __align__(128) uint8_t dyn[];
  __shared__ float rsS[128];
  const uint32_t sQ    = (uint32_t)__cvta_generic_to_shared(dyn);
  const uint32_t sRing = sQ + 2 * TILEB;
  const int tid = threadIdx.x, lane = tid & 31, warp = tid >> 5;
  const int warpM = warp & 3, warpN = warp >> 2;
  const int itile = blockIdx.x, bh = blockIdx.y;
  const int b = bh >> 4, h = bh & 15;
  const __half* qb    = Q  + (long)b * S_ * D_ + (long)h * HD_ + (long)itile * 128 * D_;
  const __half* kbase = Km + (long)b * S_ * D_ + (long)h * HD_;

  if (tid < 128) rsS[tid] = 0.0f;
  float rs[4] = {0.0f, 0.0f, 0.0f, 0.0f};

  // Q tile (128 x 128 halfs = two 64-half blocks), loaded once.
  ld_tile(sQ,         qb,      D_, tid);
  ld_tile(sQ + TILEB, qb + KB, D_, tid);
  cp_commit();

  const int nseg = 2 * (S_ / 128 - itile);
  auto ld_seg = [&](int s) {
    const int jt  = itile + (s >> 1);
    const int kb2 = s & 1;
    ld_tile(sRing + (s % NST) * TILEB,
            kbase + (long)jt * 128 * D_ + kb2 * KB, D_, tid);
    cp_commit();
  };
  ld_seg(0);
  if (nseg > 1) ld_seg(1);
  if (nseg > 2) ld_seg(2);

  float acc[2][8][4];
  for (int s = 0; s < nseg; ++s) {
    const int jt  = itile + (s >> 1);
    const int kb2 = s & 1;
    if (kb2 == 0) {
#pragma unroll
      for (int m = 0; m < 2; ++m)
#pragma unroll
        for (int n = 0; n < 8; ++n)
#pragma unroll
          for (int c = 0; c < 4; ++c) acc[m][n][c] = 0.0f;
    }
    cp_wait<NST - 1>();
    __syncthreads();
    mma_block(sQ + kb2 * TILEB, sRing + (s % NST) * TILEB,
              warpM, warpN, lane, acc);
    __syncthreads();
    if (s + NST < nseg) ld_seg(s + NST);

    if (kb2 == 1) {
      if (jt > itile) {
#pragma unroll
        for (int m = 0; m < 2; ++m)
#pragma unroll
          for (int n = 0; n < 8; ++n) {
            rs[m * 2 + 0] += __expf(acc[m][n][0] * SCALE) + __expf(acc[m][n][1] * SCALE);
            rs[m * 2 + 1] += __expf(acc[m][n][2] * SCALE) + __expf(acc[m][n][3] * SCALE);
          }
      } else {
#pragma unroll
        for (int m = 0; m < 2; ++m) {
          const int li0 = warpM * 32 + m * 16 + (lane >> 2);
#pragma unroll
          for (int n = 0; n < 8; ++n) {
            const int lj = warpN * 64 + n * 8 + (lane & 3) * 2;
#pragma unroll
            for (int c = 0; c < 4; ++c) {
              const int li  = li0 + ((c >> 1) << 3);
              const int ljc = lj + (c & 1);
              if (ljc >= li) {
                const float e = __expf(acc[m][n][c] * SCALE);
                rs[m * 2 + (c >> 1)] += e;
                if (ljc == li) ediag[(long)bh * S_ + itile * 128 + li] = e;
              }
            }
          }
        }
      }
    }
  }

#pragma unroll
  for (int r = 0; r < 4; ++r) {
    rs[r] += __shfl_xor_sync(0xffffffffu, rs[r], 1);
    rs[r] += __shfl_xor_sync(0xffffffffu, rs[r], 2);
  }
  __syncthreads();
  if ((lane & 3) == 0) {
#pragma unroll
    for (int r = 0; r < 4; ++r) {
      const int li = warpM * 32 + (r >> 1) * 16 + (r & 1) * 8 + (lane >> 2);
      atomicAdd(&rsS[li], rs[r]);
    }
  }
  __syncthreads();
  if (tid < 128) {
    const int i = itile * 128 + tid;
    dinv[(long)bh * S_ + i] = 1.0f / ((float)i + rsS[tid]);
  }
}

// ---------------------------------------------------------------------------
// fp32 -> fp16 conversion prepass (8 elems/thread).
// ---------------------------------------------------------------------------
__global__ void conv_h(const float4* __restrict__ in, uint4* __restrict__ out, int n8) {
  const int i = blockIdx.x * blockDim.x + threadIdx.x;
  if (i < n8) {
    const float4 v0 = in[2 * i], v1 = in[2 * i + 1];
    uint4 o;
    o.x = h2u(__floats2half2_rn(v0.x, v0.y));
    o.y = h2u(__floats2half2_rn(v0.z, v0.w));
    o.z = h2u(__floats2half2_rn(v1.x, v1.y));
    o.w = h2u(__floats2half2_rn(v1.z, v1.w));
    out[i] = o;
  }
}

// ---------------------------------------------------------------------------
// V prefix-sum / combine; cc written as fp16.
// ---------------------------------------------------------------------------
__global__ void scan_pass1(const float* __restrict__ V, float* __restrict__ csum) {
  const int blk = blockIdx.x;
  const int bh = blk / NC_, c = blk % NC_;
  const int b = bh / H_, h = bh % H_;
  const int hd = threadIdx.x;
  const float* vp = V + (long)b * S_ * D_ + h * HD_ + hd;
  const int i0 = c * CH_;
  float s = 0.0f;
#pragma unroll 4
  for (int r = 0; r < CH_; ++r) s += vp[(long)(i0 + r) * D_];
  csum[(bh * NC_ + c) * HD_ + hd] = s;
}

__global__ void scan_pass2(const float* __restrict__ V, const float* __restrict__ csum,
                           const float* __restrict__ dinv, const float* __restrict__ ediag,
                           __half* __restrict__ CC) {
  const int blk = blockIdx.x;
  const int bh = blk / NC_, c = blk % NC_;
  const int b = bh / H_, h = bh % H_;
  const int hd = threadIdx.x;
  const long base = (long)b * S_ * D_ + h * HD_ + hd;
  const float* vp = V + base;
  __half* op = CC + base;
  const int i0 = c * CH_;

  float run = 0.0f;
  for (int c2 = 0; c2 < c; ++c2) run += csum[(bh * NC_ + c2) * HD_ + hd];

  for (int r = 0; r < CH_; ++r) {
    const int i = i0 + r;
    const float vv = vp[(long)i * D_];
    const float e  = ediag[bh * S_ + i];
    const float di = dinv[bh * S_ + i];
    op[(long)i * D_] = __float2half_rn((run + e * vv) * di);
    run += vv;
  }
}

// ---------------------------------------------------------------------------
extern "C" void kernel_launch(void* const* d_in, const int* in_sizes, int n_in,
                              void* d_out, int out_size) {
  const float* x   = (const float*)d_in[0];
  const float* wq  = (const float*)d_in[1];
  const float* wqb = (const float*)d_in[2];
  const float* wk  = (const float*)d_in[3];
  const float* wkb = (const float*)d_in[4];
  const float* wv  = (const float*)d_in[5];
  const float* wvb = (const float*)d_in[6];
  const float* wo  = (const float*)d_in[7];
  const float* wob = (const float*)d_in[8];
  float* out = (float*)d_out;

  __half *xh, *wqh, *wkh, *wvh, *woh, *qh, *kh, *cch;
  float *v, *dinv, *ediag, *csum;
  cudaGetSymbolAddress((void**)&xh,    g_xh);
  cudaGetSymbolAddress((void**)&wqh,   g_wqh);
  cudaGetSymbolAddress((void**)&wkh,   g_wkh);
  cudaGetSymbolAddress((void**)&wvh,   g_wvh);
  cudaGetSymbolAddress((void**)&woh,   g_woh);
  cudaGetSymbolAddress((void**)&qh,    g_qh);
  cudaGetSymbolAddress((void**)&kh,    g_kh);
  cudaGetSymbolAddress((void**)&cch,   g_cch);
  cudaGetSymbolAddress((void**)&v,     g_v);
  cudaGetSymbolAddress((void**)&dinv,  g_dinv);
  cudaGetSymbolAddress((void**)&ediag, g_ediag);
  cudaGetSymbolAddress((void**)&csum,  g_csum);

  cudaFuncSetAttribute(gemm_h,      cudaFuncAttributeMaxDynamicSharedMemorySize, DS_GEMM);
  cudaFuncSetAttribute(qk_rowsum_h, cudaFuncAttributeMaxDynamicSharedMemorySize, DS_QK);

  const int nx8 = M_ * D_ / 8;
  const int nw8 = D_ * D_ / 8;
  conv_h<<<(nx8 + 255) / 256, 256>>>((const float4*)x,  (uint4*)xh,  nx8);
  conv_h<<<(nw8 + 255) / 256, 256>>>((const float4*)wq, (uint4*)wqh, nw8);
  conv_h<<<(nw8 + 255) / 256, 256>>>((const float4*)wk, (uint4*)wkh, nw8);
  conv_h<<<(nw8 + 255) / 256, 256>>>((const float4*)wv, (uint4*)wvh, nw8);
  conv_h<<<(nw8 + 255) / 256, 256>>>((const float4*)wo, (uint4*)woh, nw8);

  const dim3 gg(D_ / 128, M_ / 128);   // (16, 32)
  gemm_h<<<gg, 256, DS_GEMM>>>(xh, wqh, wqb, qh, nullptr, D_);
  gemm_h<<<gg, 256, DS_GEMM>>>(xh, wkh, wkb, kh, nullptr, D_);
  gemm_h<<<gg, 256, DS_GEMM>>>(xh, wvh, wvb, nullptr, v, D_);

  const dim3 gr(S_ / 128, BH_);        // (16, 32)
  qk_rowsum_h<<<gr, 256, DS_QK>>>(qh, kh, dinv, ediag);

  scan_pass1<<<BH_ * NC_, HD_>>>(v, csum);
  scan_pass2<<<BH_ * NC_, HD_>>>(v, csum, dinv, ediag, cch);

  gemm_h<<<gg, 256, DS_GEMM>>>(cch, woh, wob, nullptr, out, D_);
}